// round 14
// baseline (speedup 1.0000x reference)
#include <cuda_runtime.h>
#include <cuda_bf16.h>
#include <cstdint>

#define B_N 262144
#define C_N 256
#define D_N 64
#define O_N 8
#define NTILES 2048          // B_N / 128
#define NCTA 296             // 2 per SM, persistent
#define THREADS 128          // 4 warps, 32 rows each

// ---- shared memory byte offsets ----
#define OFF_CHI 0            // centers hi bf16: 256 rows x 128B   32768
#define OFF_CLO 32768        // centers lo                         32768
#define OFF_XHI 65536        // x hi: 128 rows x 128B              16384
#define OFF_XLO 81920        // x lo                               16384
#define OFF_SK  98304        // 256 x float2 (s2, k2)               2048
#define OFF_RW  100352       // permuted [nb][k][lq] 16B chunks     8192
#define OFF_XSQ 108544       // 128 f32                              512
#define SMEM_BYTES 109056

typedef unsigned long long ull;

static __device__ __forceinline__ uint32_t smem_u32(const void* p) {
    uint32_t a;
    asm("{ .reg .u64 t; cvta.to.shared.u64 t, %1; cvt.u32.u64 %0, t; }"
        : "=r"(a) : "l"(p));
    return a;
}
static __device__ __forceinline__ float ex2f(float x) {
    float r; asm("ex2.approx.f32 %0, %1;" : "=f"(r) : "f"(x)); return r;
}
static __device__ __forceinline__ ull ffma2(ull a, ull b, ull c) {
    ull d; asm("fma.rn.f32x2 %0, %1, %2, %3;" : "=l"(d) : "l"(a), "l"(b), "l"(c));
    return d;
}
static __device__ __forceinline__ float2 unpack2(ull v) {
    float2 r; asm("mov.b64 {%0, %1}, %2;" : "=f"(r.x), "=f"(r.y) : "l"(v)); return r;
}
static __device__ __forceinline__ ull pack2(float a) {
    ull r; asm("mov.b64 %0, {%1, %2};" : "=l"(r) : "f"(a), "f"(a)); return r;
}

// swizzled byte address of a 16B granule: row stride 128B, XOR swizzle on quads
static __device__ __forceinline__ uint32_t swz(uint32_t base, int row, int kb) {
    return base + row * 128 + (kb ^ ((row & 7) << 4));
}

static __device__ __forceinline__ void ldsm4(uint32_t& r0, uint32_t& r1,
                                             uint32_t& r2, uint32_t& r3,
                                             uint32_t a) {
    asm volatile("ldmatrix.sync.aligned.m8n8.x4.shared.b16 {%0,%1,%2,%3}, [%4];"
                 : "=r"(r0), "=r"(r1), "=r"(r2), "=r"(r3) : "r"(a));
}

static __device__ __forceinline__ void mma16816(float* d, const uint32_t* a,
                                                uint32_t b0, uint32_t b1) {
    asm volatile(
        "mma.sync.aligned.m16n8k16.row.col.f32.bf16.bf16.f32 "
        "{%0,%1,%2,%3}, {%4,%5,%6,%7}, {%8,%9}, {%0,%1,%2,%3};"
        : "+f"(d[0]), "+f"(d[1]), "+f"(d[2]), "+f"(d[3])
        : "r"(a[0]), "r"(a[1]), "r"(a[2]), "r"(a[3]), "r"(b0), "r"(b1));
}

// split 2 floats into packed bf16 hi pair + lo (residual) pair
static __device__ __forceinline__ void split2(float f0, float f1,
                                              uint32_t& hi, uint32_t& lo) {
    __nv_bfloat16 b0 = __float2bfloat16_rn(f0);
    __nv_bfloat16 b1 = __float2bfloat16_rn(f1);
    float l0 = f0 - __bfloat162float(b0);
    float l1 = f1 - __bfloat162float(b1);
    __nv_bfloat162 hp; hp.x = b0; hp.y = b1;
    __nv_bfloat162 lp = __floats2bfloat162_rn(l0, l1);
    hi = *reinterpret_cast<uint32_t*>(&hp);
    lo = *reinterpret_cast<uint32_t*>(&lp);
}

// stage one float4 (quad q of a 64-float row) as bf16 hi/lo, swizzled
static __device__ __forceinline__ void stage_f4(char* smemc, uint32_t hibase,
                                                uint32_t lobase, int row, int q,
                                                float4 v) {
    uint32_t h0, l0, h1, l1;
    split2(v.x, v.y, h0, l0);
    split2(v.z, v.w, h1, l1);
    int off = row * 128 + (((q >> 1) * 16) ^ ((row & 7) << 4)) + (q & 1) * 8;
    *reinterpret_cast<uint2*>(smemc + hibase + off) = make_uint2(h0, h1);
    *reinterpret_cast<uint2*>(smemc + lobase + off) = make_uint2(l0, l1);
}

// per-nb register-resident operands: B fragments + sk + rw
struct BFrag {
    uint32_t bh[8], bl[8];
    float4 skv;
    ulonglong2 w0, w1, w2, w3;
};

__global__ void __launch_bounds__(THREADS, 2)
fuzzy_mma(const float* __restrict__ x,
          const float* __restrict__ centers,
          const float* __restrict__ widths,
          const float* __restrict__ rw,
          float* __restrict__ out) {
    extern __shared__ __align__(1024) char smemc[];
    float* smf = reinterpret_cast<float*>(smemc);
    const uint32_t su = smem_u32(smemc);
    const int tid = threadIdx.x;
    const int wid = tid >> 5;
    const int lane = tid & 31;
    const int lq = lane & 3;
    const int bid = blockIdx.x;

    // ========== one-time: centers -> bf16 hi/lo (coalesced), sk, rw ==========
    {
        const float4* cg = reinterpret_cast<const float4*>(centers);
        const float LOG2E = 1.4426950408889634f;
#pragma unroll 4
        for (int i = 0; i < 32; i++) {
            int j = tid + i * THREADS;          // float4 index, 4096 total
            float4 v = cg[j];
            float p = v.x * v.x;
            p = fmaf(v.y, v.y, p);
            p = fmaf(v.z, v.z, p);
            p = fmaf(v.w, v.w, p);
            p += __shfl_xor_sync(0xffffffffu, p, 1);
            p += __shfl_xor_sync(0xffffffffu, p, 2);
            p += __shfl_xor_sync(0xffffffffu, p, 4);
            p += __shfl_xor_sync(0xffffffffu, p, 8);
            stage_f4(smemc, OFF_CHI, OFF_CLO, j >> 4, j & 15, v);
            if ((tid & 15) == 0) {
                int row = j >> 4;
                float w = widths[row];
                float s = LOG2E / (2.f * w * w);
                smf[OFF_SK / 4 + 2 * row] = s;
                smf[OFF_SK / 4 + 2 * row + 1] = -p * s;
            }
        }
        // rw permuted: new[nb*16 + k*4 + lq] = orig[nb*16 + lq*4 + k]
        const float4* rg = reinterpret_cast<const float4*>(rw);
        float4* rs = reinterpret_cast<float4*>(smemc + OFF_RW);
#pragma unroll
        for (int i = 0; i < 4; i++) {
            int n = tid + i * THREADS;
            int orig = (n & ~15) | ((n & 3) << 2) | ((n >> 2) & 3);
            rs[n] = rg[orig];
        }
    }
    __syncthreads();

    // ldmatrix lane address components (constant per thread)
    const int la_row = ((lane >> 3) & 1) * 8 + (lane & 7);   // A: row within 16
    const int la_k16 = (lane >> 4);                          // A: +16B for k+8
    const int lb_row = lane & 7;                             // B: n within 8
    const int lb_k16 = (lane >> 3);                          // B: granule 0..3
    const int m0 = wid * 32;

    // ================= persistent tile loop =================
    for (int tile = bid; tile < NTILES; tile += NCTA) {
        // ---- stage x tile: coalesced read + shfl xsq + swizzled store ----
        {
            const float4* xg = reinterpret_cast<const float4*>(x) + (size_t)tile * 2048;
#pragma unroll 4
            for (int i = 0; i < 16; i++) {
                int j = tid + i * THREADS;
                float4 v = xg[j];
                float p = v.x * v.x;
                p = fmaf(v.y, v.y, p);
                p = fmaf(v.z, v.z, p);
                p = fmaf(v.w, v.w, p);
                p += __shfl_xor_sync(0xffffffffu, p, 1);
                p += __shfl_xor_sync(0xffffffffu, p, 2);
                p += __shfl_xor_sync(0xffffffffu, p, 4);
                p += __shfl_xor_sync(0xffffffffu, p, 8);
                stage_f4(smemc, OFF_XHI, OFF_XLO, j >> 4, j & 15, v);
                if ((tid & 15) == 0) smf[OFF_XSQ / 4 + (j >> 4)] = p;
            }
        }
        __syncthreads();

        // ---- A fragments: 32 rows per warp = two 16-row groups ----
        uint32_t ah0[16], al0[16], ah1[16], al1[16];
#pragma unroll
        for (int s = 0; s < 4; s++) {
            int r0 = m0 + la_row;
            int r1 = r0 + 16;
            int kb = s * 32 + la_k16 * 16;
            ldsm4(ah0[4 * s], ah0[4 * s + 1], ah0[4 * s + 2], ah0[4 * s + 3],
                  swz(su + OFF_XHI, r0, kb));
            ldsm4(al0[4 * s], al0[4 * s + 1], al0[4 * s + 2], al0[4 * s + 3],
                  swz(su + OFF_XLO, r0, kb));
            ldsm4(ah1[4 * s], ah1[4 * s + 1], ah1[4 * s + 2], ah1[4 * s + 3],
                  swz(su + OFF_XHI, r1, kb));
            ldsm4(al1[4 * s], al1[4 * s + 1], al1[4 * s + 2], al1[4 * s + 3],
                  swz(su + OFF_XLO, r1, kb));
        }
        float xs0 = smf[OFF_XSQ / 4 + m0 + (lane >> 2)];
        float xs1 = smf[OFF_XSQ / 4 + m0 + (lane >> 2) + 8];
        float xs2 = smf[OFF_XSQ / 4 + m0 + (lane >> 2) + 16];
        float xs3 = smf[OFF_XSQ / 4 + m0 + (lane >> 2) + 24];

        float den0 = 0.f, den1 = 0.f, den2 = 0.f, den3 = 0.f;
        ull num0[4] = {0, 0, 0, 0};
        ull num1[4] = {0, 0, 0, 0};
        ull num2[4] = {0, 0, 0, 0};
        ull num3[4] = {0, 0, 0, 0};

        // ---- n-block loop over 256 clusters (single-buffered operands) ----
#pragma unroll 2
        for (int nb = 0; nb < 32; nb++) {
            BFrag F;
            {
                const int n0 = nb * 8;
#pragma unroll
                for (int p = 0; p < 2; p++) {
                    int row = n0 + lb_row;
                    int kb = p * 64 + lb_k16 * 16;
                    ldsm4(F.bh[4 * p], F.bh[4 * p + 1], F.bh[4 * p + 2], F.bh[4 * p + 3],
                          swz(su + OFF_CHI, row, kb));
                    ldsm4(F.bl[4 * p], F.bl[4 * p + 1], F.bl[4 * p + 2], F.bl[4 * p + 3],
                          swz(su + OFF_CLO, row, kb));
                }
                F.skv = *reinterpret_cast<const float4*>(
                    smemc + OFF_SK + n0 * 8 + lq * 16);
                const ulonglong2* wp = reinterpret_cast<const ulonglong2*>(
                    smemc + OFF_RW + nb * 256 + lq * 16);
                F.w0 = wp[0];
                F.w1 = wp[4];
                F.w2 = wp[8];
                F.w3 = wp[12];
            }

            // ---- 6 independent accumulator chains (depth 4 each) ----
            float hh0[4] = {0.f, 0.f, 0.f, 0.f};
            float hl0[4] = {0.f, 0.f, 0.f, 0.f};
            float lh0[4] = {0.f, 0.f, 0.f, 0.f};
            float hh1[4] = {0.f, 0.f, 0.f, 0.f};
            float hl1[4] = {0.f, 0.f, 0.f, 0.f};
            float lh1[4] = {0.f, 0.f, 0.f, 0.f};
#pragma unroll
            for (int s = 0; s < 4; s++) {
                int bi = (s >> 1) * 4 + (s & 1) * 2;
                mma16816(hh0, &ah0[4 * s], F.bh[bi], F.bh[bi + 1]);
                mma16816(hh1, &ah1[4 * s], F.bh[bi], F.bh[bi + 1]);
                mma16816(hl0, &ah0[4 * s], F.bl[bi], F.bl[bi + 1]);
                mma16816(hl1, &ah1[4 * s], F.bl[bi], F.bl[bi + 1]);
                mma16816(lh0, &al0[4 * s], F.bh[bi], F.bh[bi + 1]);
                mma16816(lh1, &al1[4 * s], F.bh[bi], F.bh[bi + 1]);
            }
            float acc0[4], acc1[4];
#pragma unroll
            for (int i = 0; i < 4; i++) {
                acc0[i] = (hh0[i] + hl0[i]) + lh0[i];
                acc1[i] = (hh1[i] + hl1[i]) + lh1[i];
            }

            // epilogue g0
            {
                float m00 = ex2f(fmaf(F.skv.x, fmaf(acc0[0], 2.f, -xs0), F.skv.y));
                float m01 = ex2f(fmaf(F.skv.z, fmaf(acc0[1], 2.f, -xs0), F.skv.w));
                float m10 = ex2f(fmaf(F.skv.x, fmaf(acc0[2], 2.f, -xs1), F.skv.y));
                float m11 = ex2f(fmaf(F.skv.z, fmaf(acc0[3], 2.f, -xs1), F.skv.w));
                den0 += m00 + m01;
                den1 += m10 + m11;
                ull mA0 = pack2(m00), mB0 = pack2(m01);
                ull mA1 = pack2(m10), mB1 = pack2(m11);
                num0[0] = ffma2(mA0, F.w0.x, num0[0]);
                num0[1] = ffma2(mA0, F.w0.y, num0[1]);
                num0[2] = ffma2(mA0, F.w1.x, num0[2]);
                num0[3] = ffma2(mA0, F.w1.y, num0[3]);
                num0[0] = ffma2(mB0, F.w2.x, num0[0]);
                num0[1] = ffma2(mB0, F.w2.y, num0[1]);
                num0[2] = ffma2(mB0, F.w3.x, num0[2]);
                num0[3] = ffma2(mB0, F.w3.y, num0[3]);
                num1[0] = ffma2(mA1, F.w0.x, num1[0]);
                num1[1] = ffma2(mA1, F.w0.y, num1[1]);
                num1[2] = ffma2(mA1, F.w1.x, num1[2]);
                num1[3] = ffma2(mA1, F.w1.y, num1[3]);
                num1[0] = ffma2(mB1, F.w2.x, num1[0]);
                num1[1] = ffma2(mB1, F.w2.y, num1[1]);
                num1[2] = ffma2(mB1, F.w3.x, num1[2]);
                num1[3] = ffma2(mB1, F.w3.y, num1[3]);
            }
            // epilogue g1
            {
                float m00 = ex2f(fmaf(F.skv.x, fmaf(acc1[0], 2.f, -xs2), F.skv.y));
                float m01 = ex2f(fmaf(F.skv.z, fmaf(acc1[1], 2.f, -xs2), F.skv.w));
                float m10 = ex2f(fmaf(F.skv.x, fmaf(acc1[2], 2.f, -xs3), F.skv.y));
                float m11 = ex2f(fmaf(F.skv.z, fmaf(acc1[3], 2.f, -xs3), F.skv.w));
                den2 += m00 + m01;
                den3 += m10 + m11;
                ull mA0 = pack2(m00), mB0 = pack2(m01);
                ull mA1 = pack2(m10), mB1 = pack2(m11);
                num2[0] = ffma2(mA0, F.w0.x, num2[0]);
                num2[1] = ffma2(mA0, F.w0.y, num2[1]);
                num2[2] = ffma2(mA0, F.w1.x, num2[2]);
                num2[3] = ffma2(mA0, F.w1.y, num2[3]);
                num2[0] = ffma2(mB0, F.w2.x, num2[0]);
                num2[1] = ffma2(mB0, F.w2.y, num2[1]);
                num2[2] = ffma2(mB0, F.w3.x, num2[2]);
                num2[3] = ffma2(mB0, F.w3.y, num2[3]);
                num3[0] = ffma2(mA1, F.w0.x, num3[0]);
                num3[1] = ffma2(mA1, F.w0.y, num3[1]);
                num3[2] = ffma2(mA1, F.w1.x, num3[2]);
                num3[3] = ffma2(mA1, F.w1.y, num3[3]);
                num3[0] = ffma2(mB1, F.w2.x, num3[0]);
                num3[1] = ffma2(mB1, F.w2.y, num3[1]);
                num3[2] = ffma2(mB1, F.w3.x, num3[2]);
                num3[3] = ffma2(mB1, F.w3.y, num3[3]);
            }
        }

        // ---- quad reduction (lane bits 0..1) ----
#pragma unroll
        for (int s = 1; s < 4; s <<= 1) {
            den0 += __shfl_xor_sync(0xffffffffu, den0, s);
            den1 += __shfl_xor_sync(0xffffffffu, den1, s);
            den2 += __shfl_xor_sync(0xffffffffu, den2, s);
            den3 += __shfl_xor_sync(0xffffffffu, den3, s);
#pragma unroll
            for (int k = 0; k < 4; k++) {
                float2 u;
                u = unpack2(num0[k]);
                u.x += __shfl_xor_sync(0xffffffffu, u.x, s);
                u.y += __shfl_xor_sync(0xffffffffu, u.y, s);
                asm("mov.b64 %0, {%1, %2};" : "=l"(num0[k]) : "f"(u.x), "f"(u.y));
                u = unpack2(num1[k]);
                u.x += __shfl_xor_sync(0xffffffffu, u.x, s);
                u.y += __shfl_xor_sync(0xffffffffu, u.y, s);
                asm("mov.b64 %0, {%1, %2};" : "=l"(num1[k]) : "f"(u.x), "f"(u.y));
                u = unpack2(num2[k]);
                u.x += __shfl_xor_sync(0xffffffffu, u.x, s);
                u.y += __shfl_xor_sync(0xffffffffu, u.y, s);
                asm("mov.b64 %0, {%1, %2};" : "=l"(num2[k]) : "f"(u.x), "f"(u.y));
                u = unpack2(num3[k]);
                u.x += __shfl_xor_sync(0xffffffffu, u.x, s);
                u.y += __shfl_xor_sync(0xffffffffu, u.y, s);
                asm("mov.b64 %0, {%1, %2};" : "=l"(num3[k]) : "f"(u.x), "f"(u.y));
            }
        }

        if ((lane & 3) == 0) {
            size_t gr = (size_t)tile * 128 + m0 + (lane >> 2);
            float inv;
            float2 u;
            float4 o;
            float4* go;
#define WRITE_ROWS(numA, denA, roff)                                        \
            inv = 1.0f / (denA);                                            \
            go = reinterpret_cast<float4*>(out + (gr + (roff)) * O_N);      \
            u = unpack2(numA[0]); o.x = u.x * inv; o.y = u.y * inv;         \
            u = unpack2(numA[1]); o.z = u.x * inv; o.w = u.y * inv;         \
            go[0] = o;                                                      \
            u = unpack2(numA[2]); o.x = u.x * inv; o.y = u.y * inv;         \
            u = unpack2(numA[3]); o.z = u.x * inv; o.w = u.y * inv;         \
            go[1] = o;
            WRITE_ROWS(num0, den0, 0)
            WRITE_ROWS(num1, den1, 8)
            WRITE_ROWS(num2, den2, 16)
            WRITE_ROWS(num3, den3, 24)
#undef WRITE_ROWS
        }
        __syncthreads();   // protect x tile before next stage
    }
}

extern "C" void kernel_launch(void* const* d_in, const int* in_sizes, int n_in,
                              void* d_out, int out_size) {
    const float* x       = (const float*)d_in[0];
    const float* centers = (const float*)d_in[1];
    const float* widths  = (const float*)d_in[2];
    const float* rw      = (const float*)d_in[3];
    float* out = (float*)d_out;

    cudaFuncSetAttribute(fuzzy_mma,
                         cudaFuncAttributeMaxDynamicSharedMemorySize, SMEM_BYTES);
    fuzzy_mma<<<NCTA, THREADS, SMEM_BYTES>>>(x, centers, widths, rw, out);
}